// round 1
// baseline (speedup 1.0000x reference)
#include <cuda_runtime.h>
#include <math.h>

#define LSEQ 2048
#define NDIM 512
#define NHEAD 8
#define HDIM 64
#define QSD 1024      // 2*DIM
#define FD 128        // per-head feature dim (cos | sin)
#define PI_F 3.14159265358979323846f
#define CSC (1024.0f / 1023.0f)

// ---------------- static device scratch (no allocations) ----------------
__device__ __align__(256) float g_qs[LSEQ * QSD];          // 8 MB
__device__ __align__(256) float g_qf[NHEAD * LSEQ * FD];   // 8 MB
__device__ __align__(256) float g_kf[NHEAD * LSEQ * FD];   // 8 MB
__device__ __align__(256) float g_v [NHEAD * LSEQ * HDIM]; // 4 MB
__device__ __align__(256) float g_ao[NHEAD * LSEQ * HDIM]; // 4 MB

// ---------------- generic 64x64-tile SIMT GEMM: C = A@B + bias ----------------
// GATHER=true: A is the head-major attention output g_ao, logically [M, 512]
// with AO[i][k] = g_ao[( (k>>6)*LSEQ + i )*64 + (k&63)].
template<bool GATHER>
__global__ __launch_bounds__(256)
void gemm64(const float* __restrict__ A, const float* __restrict__ B,
            const float* __restrict__ bias, float* __restrict__ C,
            int M, int N, int K)
{
    __shared__ float As[64 * 17];
    __shared__ float Bs[16 * 64];
    const int tid = threadIdx.x;
    const int tx = tid & 15, ty = tid >> 4;
    const int m0 = blockIdx.y << 6, n0 = blockIdx.x << 6;

    float acc[4][4] = {};

    for (int k0 = 0; k0 < K; k0 += 16) {
        // load A tile 64x16
        {
            int r  = tid >> 2;            // 0..63
            int kq = (tid & 3) << 2;      // 0,4,8,12
            float4 av;
            if (GATHER) {
                int k = k0 + kq;
                int head = k >> 6, d = k & 63;
                av = *reinterpret_cast<const float4*>(
                        &g_ao[((size_t)(head * LSEQ + (m0 + r))) * HDIM + d]);
            } else {
                av = *reinterpret_cast<const float4*>(
                        &A[(size_t)(m0 + r) * K + k0 + kq]);
            }
            As[r * 17 + kq + 0] = av.x;
            As[r * 17 + kq + 1] = av.y;
            As[r * 17 + kq + 2] = av.z;
            As[r * 17 + kq + 3] = av.w;
        }
        // load B tile 16x64
        {
            int kk = tid >> 4;            // 0..15
            int c4 = (tid & 15) << 2;     // 0..60
            float4 bv = *reinterpret_cast<const float4*>(
                    &B[(size_t)(k0 + kk) * N + n0 + c4]);
            *reinterpret_cast<float4*>(&Bs[kk * 64 + c4]) = bv;
        }
        __syncthreads();

        #pragma unroll
        for (int kk = 0; kk < 16; ++kk) {
            float a[4], b[4];
            #pragma unroll
            for (int i = 0; i < 4; ++i) a[i] = As[(ty + 16 * i) * 17 + kk];
            #pragma unroll
            for (int j = 0; j < 4; ++j) b[j] = Bs[kk * 64 + tx + 16 * j];
            #pragma unroll
            for (int i = 0; i < 4; ++i)
                #pragma unroll
                for (int j = 0; j < 4; ++j)
                    acc[i][j] += a[i] * b[j];
        }
        __syncthreads();
    }

    #pragma unroll
    for (int i = 0; i < 4; ++i) {
        int row = m0 + ty + 16 * i;
        #pragma unroll
        for (int j = 0; j < 4; ++j) {
            int col = n0 + tx + 16 * j;
            C[(size_t)row * N + col] = acc[i][j] + bias[col];
        }
    }
}

// ---------------- per-row LayerNorm + activations + sincos features ----------------
__global__ __launch_bounds__(256)
void ln_feat_kernel(const float* __restrict__ x,
                    const float* __restrict__ ln_w, const float* __restrict__ ln_b,
                    const float* __restrict__ freq, const float* __restrict__ shift)
{
    const int i = blockIdx.x;       // row 0..2047
    const int tid = threadIdx.x;
    __shared__ float sh[QSD];
    __shared__ float red[256];

    const float* row = g_qs + (size_t)i * QSD;

    // mean
    float s = 0.f;
    for (int c = tid; c < QSD; c += 256) { float v = row[c]; sh[c] = v; s += v; }
    red[tid] = s; __syncthreads();
    for (int o = 128; o > 0; o >>= 1) { if (tid < o) red[tid] += red[tid + o]; __syncthreads(); }
    const float mean = red[0] * (1.0f / QSD);
    __syncthreads();

    // variance (two-pass)
    float s2 = 0.f;
    for (int c = tid; c < QSD; c += 256) { float dv = sh[c] - mean; s2 += dv * dv; }
    red[tid] = s2; __syncthreads();
    for (int o = 128; o > 0; o >>= 1) { if (tid < o) red[tid] += red[tid + o]; __syncthreads(); }
    const float rstd = rsqrtf(red[0] * (1.0f / QSD) + 1e-5f);
    __syncthreads();

    // normalize in place
    for (int c = tid; c < QSD; c += 256)
        sh[c] = (sh[c] - mean) * rstd * ln_w[c] + ln_b[c];
    __syncthreads();

    // amp = sigmoid(first half), accumulate sum of squares
    float sa2 = 0.f;
    for (int c = tid; c < NDIM; c += 256) {
        float a = 1.0f / (1.0f + expf(-sh[c]));
        sh[c] = a;
        sa2 += a * a;
    }
    red[tid] = sa2; __syncthreads();
    for (int o = 128; o > 0; o >>= 1) { if (tid < o) red[tid] += red[tid + o]; __syncthreads(); }
    const float rnorm = 1.0f / (sqrtf(red[0]) + 1e-8f);

    // features: Q' = qa*[cos|sin](c*(f*qp+s)), K' = qa*[cos|sin](c*f*qp)
    for (int c = tid; c < NDIM; c += 256) {
        int h = c >> 6, d = c & 63;
        float qa = sh[c] * rnorm;
        float qp = tanhf(sh[NDIM + c]) * PI_F;
        float f  = freq[h];
        float sp = shift[h];
        float Bang = CSC * f * qp;
        float Aang = Bang + CSC * sp;
        float ca, sa, cb, sb;
        sincosf(Aang, &sa, &ca);
        sincosf(Bang, &sb, &cb);
        size_t base = ((size_t)(h * LSEQ + i)) * FD;
        g_qf[base + d]      = qa * ca;
        g_qf[base + 64 + d] = qa * sa;
        g_kf[base + d]      = qa * cb;
        g_kf[base + 64 + d] = qa * sb;
        g_v[((size_t)(h * LSEQ + i)) * HDIM + d] = x[(size_t)i * NDIM + c];
    }
}

// ---------------- attention: S = Q'K'^T (k=128), P = exp(S/8), O = P V / rowsum ----------------
// |score| <= 1 by Cauchy-Schwarz (amps L2-normalized), so no max-subtraction needed.
__global__ __launch_bounds__(256)
void attn_kernel()
{
    extern __shared__ float smem[];
    const int QP = 129, PP = 81;
    float* Qs   = smem;                 // 64 x 129
    float* Ks   = Qs + 64 * QP;         // 64 x 129
    float* Ps   = Ks + 64 * QP;         // 64 x 81
    float* Vs   = Ps + 64 * PP;         // 64 x 64
    float* rowl = Vs + 64 * HDIM;       // 64

    const int h  = blockIdx.y;
    const int q0 = blockIdx.x << 6;
    const int tid = threadIdx.x;
    const int tx = tid & 15, ty = tid >> 4;

    // load Q tile once
    const float* qbase = g_qf + ((size_t)(h * LSEQ + q0)) * FD;
    for (int idx = tid; idx < 64 * FD; idx += 256) {
        int r = idx >> 7, c = idx & 127;
        Qs[r * QP + c] = qbase[(size_t)r * FD + c];
    }
    if (tid < 64) rowl[tid] = 0.f;

    float acc[4][4] = {};

    for (int kt = 0; kt < LSEQ / 64; ++kt) {
        const int k0 = kt << 6;
        const float* kbase = g_kf + ((size_t)(h * LSEQ + k0)) * FD;
        for (int idx = tid; idx < 64 * FD; idx += 256) {
            int r = idx >> 7, c = idx & 127;
            Ks[r * QP + c] = kbase[(size_t)r * FD + c];
        }
        const float* vbase = g_v + ((size_t)(h * LSEQ + k0)) * HDIM;
        for (int idx = tid; idx < 64 * HDIM; idx += 256)
            Vs[idx] = vbase[idx];
        __syncthreads();

        // S = Q' K'^T
        float sacc[4][4] = {};
        #pragma unroll 8
        for (int kk = 0; kk < FD; ++kk) {
            float q[4], k[4];
            #pragma unroll
            for (int i = 0; i < 4; ++i) q[i] = Qs[(ty + 16 * i) * QP + kk];
            #pragma unroll
            for (int j = 0; j < 4; ++j) k[j] = Ks[(tx + 16 * j) * QP + kk];
            #pragma unroll
            for (int i = 0; i < 4; ++i)
                #pragma unroll
                for (int j = 0; j < 4; ++j)
                    sacc[i][j] += q[i] * k[j];
        }

        // P = exp(S * 0.125), row sums into shared
        #pragma unroll
        for (int i = 0; i < 4; ++i) {
            float rs = 0.f;
            #pragma unroll
            for (int j = 0; j < 4; ++j) {
                float p = __expf(sacc[i][j] * 0.125f);
                Ps[(ty + 16 * i) * PP + tx + 16 * j] = p;
                rs += p;
            }
            atomicAdd(&rowl[ty + 16 * i], rs);
        }
        __syncthreads();

        // acc += P @ V
        #pragma unroll 8
        for (int kk = 0; kk < 64; ++kk) {
            float p[4], v[4];
            #pragma unroll
            for (int i = 0; i < 4; ++i) p[i] = Ps[(ty + 16 * i) * PP + kk];
            #pragma unroll
            for (int j = 0; j < 4; ++j) v[j] = Vs[kk * HDIM + tx + 16 * j];
            #pragma unroll
            for (int i = 0; i < 4; ++i)
                #pragma unroll
                for (int j = 0; j < 4; ++j)
                    acc[i][j] += p[i] * v[j];
        }
        __syncthreads();
    }

    // normalize and write
    #pragma unroll
    for (int i = 0; i < 4; ++i) {
        int row = ty + 16 * i;
        float inv = 1.0f / rowl[row];
        #pragma unroll
        for (int j = 0; j < 4; ++j) {
            g_ao[((size_t)(h * LSEQ + q0 + row)) * HDIM + tx + 16 * j] = acc[i][j] * inv;
        }
    }
}

// ---------------- launch ----------------
extern "C" void kernel_launch(void* const* d_in, const int* in_sizes, int n_in,
                              void* d_out, int out_size)
{
    const float* x     = (const float*)d_in[0];
    const float* W_qs  = (const float*)d_in[1];
    const float* b_qs  = (const float*)d_in[2];
    const float* ln_w  = (const float*)d_in[3];
    const float* ln_b  = (const float*)d_in[4];
    const float* freq  = (const float*)d_in[5];
    const float* phs   = (const float*)d_in[6];
    const float* W_out = (const float*)d_in[7];
    const float* b_out = (const float*)d_in[8];
    // d_in[9] = cos_table: replaced analytically (cos(2*pi*k/1023) with k = floor(u))
    float* out = (float*)d_out;

    void* p_qs = nullptr;
    cudaGetSymbolAddress(&p_qs, g_qs);

    const size_t smem_attn = (size_t)(64 * 129 * 2 + 64 * 81 + 64 * 64 + 64) * sizeof(float);
    cudaFuncSetAttribute(attn_kernel, cudaFuncAttributeMaxDynamicSharedMemorySize, (int)smem_attn);

    // 1) qs = x @ W_qs + b_qs   [2048,1024]
    gemm64<false><<<dim3(QSD / 64, LSEQ / 64), 256>>>(x, W_qs, b_qs, (float*)p_qs,
                                                      LSEQ, QSD, NDIM);
    // 2) LN + activations + sincos features + v scatter
    ln_feat_kernel<<<LSEQ, 256>>>(x, ln_w, ln_b, freq, phs);
    // 3) attention
    attn_kernel<<<dim3(LSEQ / 64, NHEAD), 256, smem_attn>>>();
    // 4) out = AO @ W_out + b_out   [2048,512]
    gemm64<true><<<dim3(NDIM / 64, LSEQ / 64), 256>>>(nullptr, W_out, b_out, out,
                                                      LSEQ, NDIM, NDIM);
}

// round 3
// speedup vs baseline: 4.9826x; 4.9826x over previous
#include <cuda_runtime.h>
#include <cuda_fp16.h>
#include <cstdint>
#include <math.h>

#define LSEQ 2048
#define NDIM 512
#define NHEAD 8
#define HDIM 64
#define QSD 1024      // 2*DIM
#define FD 128        // per-head feature dim (cos | sin)
#define PI_F 3.14159265358979323846f
#define CSC (1024.0f / 1023.0f)

// ---------------- static device scratch (no allocations) ----------------
__device__ __align__(256) float  g_qs[LSEQ * QSD];           // 8 MB
__device__ __align__(256) __half g_qf[NHEAD * LSEQ * FD];    // 4 MB
__device__ __align__(256) __half g_kf[NHEAD * LSEQ * FD];    // 4 MB
__device__ __align__(256) __half g_v [NHEAD * LSEQ * HDIM];  // 2 MB
__device__ __align__(256) float  g_ao[NHEAD * LSEQ * HDIM];  // 4 MB

// ---------------- mma / ldmatrix helpers ----------------
__device__ __forceinline__ uint32_t smem_u32(const void* p) {
    return (uint32_t)__cvta_generic_to_shared(p);
}
__device__ __forceinline__ void ldsm_x4(uint32_t r[4], uint32_t addr) {
    asm volatile("ldmatrix.sync.aligned.m8n8.x4.shared.b16 {%0,%1,%2,%3}, [%4];"
        : "=r"(r[0]), "=r"(r[1]), "=r"(r[2]), "=r"(r[3]) : "r"(addr));
}
__device__ __forceinline__ void ldsm_x4_t(uint32_t r[4], uint32_t addr) {
    asm volatile("ldmatrix.sync.aligned.m8n8.x4.trans.shared.b16 {%0,%1,%2,%3}, [%4];"
        : "=r"(r[0]), "=r"(r[1]), "=r"(r[2]), "=r"(r[3]) : "r"(addr));
}
__device__ __forceinline__ void mma16816(float c[4], const uint32_t a0, const uint32_t a1,
                                         const uint32_t a2, const uint32_t a3,
                                         const uint32_t b0, const uint32_t b1) {
    asm volatile("mma.sync.aligned.m16n8k16.row.col.f32.f16.f16.f32 "
        "{%0,%1,%2,%3}, {%4,%5,%6,%7}, {%8,%9}, {%0,%1,%2,%3};"
        : "+f"(c[0]), "+f"(c[1]), "+f"(c[2]), "+f"(c[3])
        : "r"(a0), "r"(a1), "r"(a2), "r"(a3), "r"(b0), "r"(b1));
}
__device__ __forceinline__ uint32_t pack_h2(float x, float y) {
    __half2 h = __floats2half2_rn(x, y);
    return *reinterpret_cast<uint32_t*>(&h);
}

// ---------------- generic 64x64-tile SIMT GEMM: C = A@B + bias ----------------
template<bool GATHER>
__global__ __launch_bounds__(256)
void gemm64(const float* __restrict__ A, const float* __restrict__ B,
            const float* __restrict__ bias, float* __restrict__ C,
            int M, int N, int K)
{
    __shared__ float As[64 * 17];
    __shared__ float Bs[16 * 64];
    const int tid = threadIdx.x;
    const int tx = tid & 15, ty = tid >> 4;
    const int m0 = blockIdx.y << 6, n0 = blockIdx.x << 6;

    float acc[4][4] = {};

    for (int k0 = 0; k0 < K; k0 += 16) {
        {
            int r  = tid >> 2;
            int kq = (tid & 3) << 2;
            float4 av;
            if (GATHER) {
                int k = k0 + kq;
                int head = k >> 6, d = k & 63;
                av = *reinterpret_cast<const float4*>(
                        &g_ao[((size_t)(head * LSEQ + (m0 + r))) * HDIM + d]);
            } else {
                av = *reinterpret_cast<const float4*>(
                        &A[(size_t)(m0 + r) * K + k0 + kq]);
            }
            As[r * 17 + kq + 0] = av.x;
            As[r * 17 + kq + 1] = av.y;
            As[r * 17 + kq + 2] = av.z;
            As[r * 17 + kq + 3] = av.w;
        }
        {
            int kk = tid >> 4;
            int c4 = (tid & 15) << 2;
            float4 bv = *reinterpret_cast<const float4*>(
                    &B[(size_t)(k0 + kk) * N + n0 + c4]);
            *reinterpret_cast<float4*>(&Bs[kk * 64 + c4]) = bv;
        }
        __syncthreads();

        #pragma unroll
        for (int kk = 0; kk < 16; ++kk) {
            float a[4], b[4];
            #pragma unroll
            for (int i = 0; i < 4; ++i) a[i] = As[(ty + 16 * i) * 17 + kk];
            #pragma unroll
            for (int j = 0; j < 4; ++j) b[j] = Bs[kk * 64 + tx + 16 * j];
            #pragma unroll
            for (int i = 0; i < 4; ++i)
                #pragma unroll
                for (int j = 0; j < 4; ++j)
                    acc[i][j] += a[i] * b[j];
        }
        __syncthreads();
    }

    #pragma unroll
    for (int i = 0; i < 4; ++i) {
        int row = m0 + ty + 16 * i;
        #pragma unroll
        for (int j = 0; j < 4; ++j) {
            int col = n0 + tx + 16 * j;
            C[(size_t)row * N + col] = acc[i][j] + bias[col];
        }
    }
}

// ---------------- per-row LayerNorm + activations + sincos features (fp16 out) ----------------
__global__ __launch_bounds__(256)
void ln_feat_kernel(const float* __restrict__ x,
                    const float* __restrict__ ln_w, const float* __restrict__ ln_b,
                    const float* __restrict__ freq, const float* __restrict__ shift)
{
    const int i = blockIdx.x;
    const int tid = threadIdx.x;
    __shared__ float sh[QSD];
    __shared__ float red[256];

    const float* row = g_qs + (size_t)i * QSD;

    float s = 0.f;
    for (int c = tid; c < QSD; c += 256) { float v = row[c]; sh[c] = v; s += v; }
    red[tid] = s; __syncthreads();
    for (int o = 128; o > 0; o >>= 1) { if (tid < o) red[tid] += red[tid + o]; __syncthreads(); }
    const float mean = red[0] * (1.0f / QSD);
    __syncthreads();

    float s2 = 0.f;
    for (int c = tid; c < QSD; c += 256) { float dv = sh[c] - mean; s2 += dv * dv; }
    red[tid] = s2; __syncthreads();
    for (int o = 128; o > 0; o >>= 1) { if (tid < o) red[tid] += red[tid + o]; __syncthreads(); }
    const float rstd = rsqrtf(red[0] * (1.0f / QSD) + 1e-5f);
    __syncthreads();

    for (int c = tid; c < QSD; c += 256)
        sh[c] = (sh[c] - mean) * rstd * ln_w[c] + ln_b[c];
    __syncthreads();

    float sa2 = 0.f;
    for (int c = tid; c < NDIM; c += 256) {
        float a = 1.0f / (1.0f + expf(-sh[c]));
        sh[c] = a;
        sa2 += a * a;
    }
    red[tid] = sa2; __syncthreads();
    for (int o = 128; o > 0; o >>= 1) { if (tid < o) red[tid] += red[tid + o]; __syncthreads(); }
    const float rnorm = 1.0f / (sqrtf(red[0]) + 1e-8f);

    for (int c = tid; c < NDIM; c += 256) {
        int h = c >> 6, d = c & 63;
        float qa = sh[c] * rnorm;
        float qp = tanhf(sh[NDIM + c]) * PI_F;
        float f  = freq[h];
        float sp = shift[h];
        float Bang = CSC * f * qp;
        float Aang = Bang + CSC * sp;
        float ca, sa, cb, sb;
        sincosf(Aang, &sa, &ca);
        sincosf(Bang, &sb, &cb);
        size_t base = ((size_t)(h * LSEQ + i)) * FD;
        g_qf[base + d]      = __float2half_rn(qa * ca);
        g_qf[base + 64 + d] = __float2half_rn(qa * sa);
        g_kf[base + d]      = __float2half_rn(qa * cb);
        g_kf[base + 64 + d] = __float2half_rn(qa * sb);
        g_v[((size_t)(h * LSEQ + i)) * HDIM + d] = __float2half_rn(x[(size_t)i * NDIM + c]);
    }
}

// ---------------- tensor-core attention ----------------
// CTA = (64 q-rows, 1 head), 8 warps -> 4 warps x 16 rows (warps 0..7 map via warp&3... we use 8 warps
// as 4 row-groups x 2 (no) -> actually 256 threads = 8 warps; warp w handles rows 16*(w%4).. wait.
// Simpler: 256 threads = 8 warps, but the tile is 64 rows = 4 warps x 16. Use warp = tid>>5 in [0,8);
// warps 4..7 duplicate rows of warps 0..3? No — we launch 128 threads (4 warps).
#define KLD 136   // Q/K smem row stride (halves)
#define VLD 72    // V smem row stride (halves)

__global__ __launch_bounds__(128, 2)
void attn_kernel()
{
    __shared__ __align__(16) __half Ks[64 * KLD];
    __shared__ __align__(16) __half Vs[64 * VLD];

    const int h  = blockIdx.y;
    const int q0 = blockIdx.x << 6;
    const int tid  = threadIdx.x;
    const int warp = tid >> 5;
    const int lane = tid & 31;

    // ---- load Q tile into Ks, pull A-fragments into registers, then reuse buffer for K ----
    {
        const __half* qg = g_qf + ((size_t)(h * LSEQ + q0)) * FD;
        for (int idx = tid; idx < 64 * 16; idx += 128) {
            int r = idx >> 4, c = (idx & 15) << 3;
            *reinterpret_cast<uint4*>(&Ks[r * KLD + c]) =
                *reinterpret_cast<const uint4*>(&qg[(size_t)r * FD + c]);
        }
    }
    __syncthreads();

    uint32_t qf[8][4];
    {
        int row = warp * 16 + (lane & 15);
        int cof = (lane >> 4) << 3;
        #pragma unroll
        for (int ks = 0; ks < 8; ++ks)
            ldsm_x4(qf[ks], smem_u32(&Ks[row * KLD + ks * 16 + cof]));
    }

    float oacc[8][4] = {};
    float rl0 = 0.f, rl1 = 0.f;

    for (int kt = 0; kt < LSEQ / 64; ++kt) {
        const int k0 = kt << 6;
        __syncthreads();   // previous tile fully consumed (and Q frags pulled on kt==0)
        {
            const __half* kg = g_kf + ((size_t)(h * LSEQ + k0)) * FD;
            for (int idx = tid; idx < 64 * 16; idx += 128) {
                int r = idx >> 4, c = (idx & 15) << 3;
                *reinterpret_cast<uint4*>(&Ks[r * KLD + c]) =
                    *reinterpret_cast<const uint4*>(&kg[(size_t)r * FD + c]);
            }
            const __half* vg = g_v + ((size_t)(h * LSEQ + k0)) * HDIM;
            for (int idx = tid; idx < 64 * 8; idx += 128) {
                int r = idx >> 3, c = (idx & 7) << 3;
                *reinterpret_cast<uint4*>(&Vs[r * VLD + c]) =
                    *reinterpret_cast<const uint4*>(&vg[(size_t)r * HDIM + c]);
            }
        }
        __syncthreads();

        // ---- S = Q' K'^T : sacc[nt] covers rows 16*warp..+15, cols 8nt..8nt+7 ----
        float sacc[8][4] = {};
        #pragma unroll
        for (int sp = 0; sp < 4; ++sp) {      // pairs of k16 steps over FD=128
            #pragma unroll
            for (int nt = 0; nt < 8; ++nt) {
                uint32_t kf[4];
                ldsm_x4(kf, smem_u32(&Ks[(nt * 8 + (lane & 7)) * KLD
                                         + sp * 32 + ((lane >> 3) << 3)]));
                mma16816(sacc[nt], qf[2 * sp][0], qf[2 * sp][1], qf[2 * sp][2], qf[2 * sp][3],
                         kf[0], kf[1]);
                mma16816(sacc[nt], qf[2 * sp + 1][0], qf[2 * sp + 1][1],
                         qf[2 * sp + 1][2], qf[2 * sp + 1][3], kf[2], kf[3]);
            }
        }

        // ---- P = exp(S/8); rowsum; repack C-frags as fp16 A-frags (layout identity) ----
        uint32_t pf[8][2];
        #pragma unroll
        for (int nt = 0; nt < 8; ++nt) {
            float e0 = __expf(sacc[nt][0] * 0.125f);
            float e1 = __expf(sacc[nt][1] * 0.125f);
            float e2 = __expf(sacc[nt][2] * 0.125f);
            float e3 = __expf(sacc[nt][3] * 0.125f);
            rl0 += e0 + e1;
            rl1 += e2 + e3;
            pf[nt][0] = pack_h2(e0, e1);
            pf[nt][1] = pack_h2(e2, e3);
        }

        // ---- O += P @ V ----
        #pragma unroll
        for (int sp = 0; sp < 2; ++sp) {      // two k32 chunks over the 64 k-rows of V
            int vrow = sp * 32 + ((lane >> 3) << 3) + (lane & 7);
            #pragma unroll
            for (int nt = 0; nt < 8; ++nt) {
                uint32_t vf[4];
                ldsm_x4_t(vf, smem_u32(&Vs[vrow * VLD + nt * 8]));
                mma16816(oacc[nt], pf[4 * sp][0], pf[4 * sp][1],
                         pf[4 * sp + 1][0], pf[4 * sp + 1][1], vf[0], vf[1]);
                mma16816(oacc[nt], pf[4 * sp + 2][0], pf[4 * sp + 2][1],
                         pf[4 * sp + 3][0], pf[4 * sp + 3][1], vf[2], vf[3]);
            }
        }
    }

    // ---- reduce rowsums across the 4 lanes of each quad-row group, normalize, store ----
    rl0 += __shfl_xor_sync(0xffffffffu, rl0, 1);
    rl0 += __shfl_xor_sync(0xffffffffu, rl0, 2);
    rl1 += __shfl_xor_sync(0xffffffffu, rl1, 1);
    rl1 += __shfl_xor_sync(0xffffffffu, rl1, 2);
    const float inv0 = 1.0f / rl0;
    const float inv1 = 1.0f / rl1;

    const int g   = lane >> 2;
    const int tig = lane & 3;
    const int row0 = h * LSEQ + q0 + warp * 16 + g;
    #pragma unroll
    for (int nt = 0; nt < 8; ++nt) {
        int col = nt * 8 + tig * 2;
        float2 lo = make_float2(oacc[nt][0] * inv0, oacc[nt][1] * inv0);
        float2 hi = make_float2(oacc[nt][2] * inv1, oacc[nt][3] * inv1);
        *reinterpret_cast<float2*>(&g_ao[(size_t)row0 * HDIM + col])       = lo;
        *reinterpret_cast<float2*>(&g_ao[(size_t)(row0 + 8) * HDIM + col]) = hi;
    }
}

// ---------------- launch ----------------
extern "C" void kernel_launch(void* const* d_in, const int* in_sizes, int n_in,
                              void* d_out, int out_size)
{
    const float* x     = (const float*)d_in[0];
    const float* W_qs  = (const float*)d_in[1];
    const float* b_qs  = (const float*)d_in[2];
    const float* ln_w  = (const float*)d_in[3];
    const float* ln_b  = (const float*)d_in[4];
    const float* freq  = (const float*)d_in[5];
    const float* phs   = (const float*)d_in[6];
    const float* W_out = (const float*)d_in[7];
    const float* b_out = (const float*)d_in[8];
    float* out = (float*)d_out;

    void* p_qs = nullptr;
    cudaGetSymbolAddress(&p_qs, g_qs);

    // 1) qs = x @ W_qs + b_qs   [2048,1024]
    gemm64<false><<<dim3(QSD / 64, LSEQ / 64), 256>>>(x, W_qs, b_qs, (float*)p_qs,
                                                      LSEQ, QSD, NDIM);
    // 2) LN + activations + sincos features (fp16) + v scatter (fp16)
    ln_feat_kernel<<<LSEQ, 256>>>(x, ln_w, ln_b, freq, phs);
    // 3) tensor-core attention (128 threads = 4 warps per 64-row tile)
    attn_kernel<<<dim3(LSEQ / 64, NHEAD), 128>>>();
    // 4) out = AO @ W_out + b_out   [2048,512]
    gemm64<true><<<dim3(NDIM / 64, LSEQ / 64), 256>>>(nullptr, W_out, b_out, out,
                                                      LSEQ, NDIM, NDIM);
}

// round 4
// speedup vs baseline: 7.0529x; 1.4155x over previous
#include <cuda_runtime.h>
#include <cuda_fp16.h>
#include <cstdint>
#include <math.h>

#define LSEQ 2048
#define NDIM 512
#define NHEAD 8
#define HDIM 64
#define QSD 1024      // 2*DIM
#define FD 128        // per-head feature dim (cos | sin)
#define PI_F 3.14159265358979323846f
#define CSC (1024.0f / 1023.0f)

// ---------------- static device scratch (no allocations) ----------------
__device__ __align__(256) float  g_qs[LSEQ * QSD];           // 8 MB
__device__ __align__(256) __half g_qf[NHEAD * LSEQ * FD];    // 4 MB
__device__ __align__(256) __half g_kf[NHEAD * LSEQ * FD];    // 4 MB
__device__ __align__(256) __half g_v [NHEAD * LSEQ * HDIM];  // 2 MB
// split fp16 operands
__device__ __align__(256) __half g_xh[LSEQ * NDIM];          // x hi
__device__ __align__(256) __half g_xl[LSEQ * NDIM];          // x lo
__device__ __align__(256) __half g_w1h[QSD * NDIM];          // W_qs^T hi  [N][K]
__device__ __align__(256) __half g_w1l[QSD * NDIM];
__device__ __align__(256) __half g_woh[NDIM * NDIM];         // W_out^T hi [N][K]
__device__ __align__(256) __half g_wol[NDIM * NDIM];
__device__ __align__(256) __half g_aoh[LSEQ * NDIM];         // attn out hi (gathered layout)
__device__ __align__(256) __half g_aol[LSEQ * NDIM];

// ---------------- mma / ldmatrix helpers ----------------
__device__ __forceinline__ uint32_t smem_u32(const void* p) {
    return (uint32_t)__cvta_generic_to_shared(p);
}
__device__ __forceinline__ void ldsm_x4(uint32_t r[4], uint32_t addr) {
    asm volatile("ldmatrix.sync.aligned.m8n8.x4.shared.b16 {%0,%1,%2,%3}, [%4];"
        : "=r"(r[0]), "=r"(r[1]), "=r"(r[2]), "=r"(r[3]) : "r"(addr));
}
__device__ __forceinline__ void ldsm_x4_t(uint32_t r[4], uint32_t addr) {
    asm volatile("ldmatrix.sync.aligned.m8n8.x4.trans.shared.b16 {%0,%1,%2,%3}, [%4];"
        : "=r"(r[0]), "=r"(r[1]), "=r"(r[2]), "=r"(r[3]) : "r"(addr));
}
__device__ __forceinline__ void mma16816(float c[4], const uint32_t a0, const uint32_t a1,
                                         const uint32_t a2, const uint32_t a3,
                                         const uint32_t b0, const uint32_t b1) {
    asm volatile("mma.sync.aligned.m16n8k16.row.col.f32.f16.f16.f32 "
        "{%0,%1,%2,%3}, {%4,%5,%6,%7}, {%8,%9}, {%0,%1,%2,%3};"
        : "+f"(c[0]), "+f"(c[1]), "+f"(c[2]), "+f"(c[3])
        : "r"(a0), "r"(a1), "r"(a2), "r"(a3), "r"(b0), "r"(b1));
}
__device__ __forceinline__ uint32_t pack_h2(float x, float y) {
    __half2 h = __floats2half2_rn(x, y);
    return *reinterpret_cast<uint32_t*>(&h);
}

// ---------------- split helpers ----------------
__global__ __launch_bounds__(256)
void split_kernel(const float* __restrict__ src, __half* __restrict__ hi,
                  __half* __restrict__ lo, int n)
{
    int i = blockIdx.x * 256 + threadIdx.x;
    if (i < n) {
        float v = src[i];
        __half h = __float2half_rn(v);
        hi[i] = h;
        lo[i] = __float2half_rn(v - __half2float(h));
    }
}

// src[R][C] -> dst[C][R] with hi/lo split (dst-linear indexing: coalesced writes)
__global__ __launch_bounds__(256)
void split_tr_kernel(const float* __restrict__ src, __half* __restrict__ hi,
                     __half* __restrict__ lo, int R, int C)
{
    int i = blockIdx.x * 256 + threadIdx.x;
    if (i < R * C) {
        int c = i / R, r = i - c * R;
        float v = src[(size_t)r * C + c];
        __half h = __float2half_rn(v);
        hi[i] = h;
        lo[i] = __float2half_rn(v - __half2float(h));
    }
}

// ---------------- HMMA GEMM with exact 3-term fp16 split ----------------
// C[M,N] = A@B + bias, where A given as (Ah+Al) row-major [M][K],
// B given transposed as (Bh+Bl) [N][K]. CTA tile 64x64, 4 warps x 16 rows.
#define GLD 72

__global__ __launch_bounds__(128)
void hmma_gemm(const __half* __restrict__ Ah, const __half* __restrict__ Al,
               const __half* __restrict__ Bh, const __half* __restrict__ Bl,
               const float* __restrict__ bias, float* __restrict__ C,
               int N, int K)
{
    __shared__ __align__(16) __half sAh[64 * GLD];
    __shared__ __align__(16) __half sAl[64 * GLD];
    __shared__ __align__(16) __half sBh[64 * GLD];
    __shared__ __align__(16) __half sBl[64 * GLD];

    const int tid  = threadIdx.x;
    const int warp = tid >> 5;
    const int lane = tid & 31;
    const int m0 = blockIdx.y << 6, n0 = blockIdx.x << 6;

    float acc[8][4] = {};

    for (int k0 = 0; k0 < K; k0 += 64) {
        if (k0) __syncthreads();
        for (int idx = tid; idx < 64 * 8; idx += 128) {
            int r = idx >> 3, c = (idx & 7) << 3;
            *reinterpret_cast<uint4*>(&sAh[r * GLD + c]) =
                *reinterpret_cast<const uint4*>(&Ah[(size_t)(m0 + r) * K + k0 + c]);
            *reinterpret_cast<uint4*>(&sAl[r * GLD + c]) =
                *reinterpret_cast<const uint4*>(&Al[(size_t)(m0 + r) * K + k0 + c]);
            *reinterpret_cast<uint4*>(&sBh[r * GLD + c]) =
                *reinterpret_cast<const uint4*>(&Bh[(size_t)(n0 + r) * K + k0 + c]);
            *reinterpret_cast<uint4*>(&sBl[r * GLD + c]) =
                *reinterpret_cast<const uint4*>(&Bl[(size_t)(n0 + r) * K + k0 + c]);
        }
        __syncthreads();

        #pragma unroll
        for (int sp2 = 0; sp2 < 2; ++sp2) {   // two k32 chunks
            const int arow = warp * 16 + (lane & 15);
            const int acol = sp2 * 32 + ((lane >> 4) << 3);
            uint32_t ah0[4], ah1[4], al0[4], al1[4];
            ldsm_x4(ah0, smem_u32(&sAh[arow * GLD + acol]));
            ldsm_x4(ah1, smem_u32(&sAh[arow * GLD + acol + 16]));
            ldsm_x4(al0, smem_u32(&sAl[arow * GLD + acol]));
            ldsm_x4(al1, smem_u32(&sAl[arow * GLD + acol + 16]));

            const int brow_base = lane & 7;
            const int bcol = sp2 * 32 + ((lane >> 3) << 3);
            #pragma unroll
            for (int nt = 0; nt < 8; ++nt) {
                uint32_t bh[4], bl[4];
                ldsm_x4(bh, smem_u32(&sBh[(nt * 8 + brow_base) * GLD + bcol]));
                ldsm_x4(bl, smem_u32(&sBl[(nt * 8 + brow_base) * GLD + bcol]));
                // Ah*Bh
                mma16816(acc[nt], ah0[0], ah0[1], ah0[2], ah0[3], bh[0], bh[1]);
                mma16816(acc[nt], ah1[0], ah1[1], ah1[2], ah1[3], bh[2], bh[3]);
                // Ah*Bl
                mma16816(acc[nt], ah0[0], ah0[1], ah0[2], ah0[3], bl[0], bl[1]);
                mma16816(acc[nt], ah1[0], ah1[1], ah1[2], ah1[3], bl[2], bl[3]);
                // Al*Bh
                mma16816(acc[nt], al0[0], al0[1], al0[2], al0[3], bh[0], bh[1]);
                mma16816(acc[nt], al1[0], al1[1], al1[2], al1[3], bh[2], bh[3]);
            }
        }
    }

    const int g   = lane >> 2;
    const int tig = lane & 3;
    const int row0 = m0 + warp * 16 + g;
    #pragma unroll
    for (int nt = 0; nt < 8; ++nt) {
        int col = n0 + nt * 8 + tig * 2;
        C[(size_t)row0 * N + col]           = acc[nt][0] + bias[col];
        C[(size_t)row0 * N + col + 1]       = acc[nt][1] + bias[col + 1];
        C[(size_t)(row0 + 8) * N + col]     = acc[nt][2] + bias[col];
        C[(size_t)(row0 + 8) * N + col + 1] = acc[nt][3] + bias[col + 1];
    }
}

// ---------------- per-row LayerNorm + activations + sincos features (fp16 out) ----------------
__global__ __launch_bounds__(256)
void ln_feat_kernel(const float* __restrict__ x,
                    const float* __restrict__ ln_w, const float* __restrict__ ln_b,
                    const float* __restrict__ freq, const float* __restrict__ shift)
{
    const int i = blockIdx.x;
    const int tid = threadIdx.x;
    __shared__ float sh[QSD];
    __shared__ float red[256];

    const float* row = g_qs + (size_t)i * QSD;

    float s = 0.f;
    for (int c = tid; c < QSD; c += 256) { float v = row[c]; sh[c] = v; s += v; }
    red[tid] = s; __syncthreads();
    for (int o = 128; o > 0; o >>= 1) { if (tid < o) red[tid] += red[tid + o]; __syncthreads(); }
    const float mean = red[0] * (1.0f / QSD);
    __syncthreads();

    float s2 = 0.f;
    for (int c = tid; c < QSD; c += 256) { float dv = sh[c] - mean; s2 += dv * dv; }
    red[tid] = s2; __syncthreads();
    for (int o = 128; o > 0; o >>= 1) { if (tid < o) red[tid] += red[tid + o]; __syncthreads(); }
    const float rstd = rsqrtf(red[0] * (1.0f / QSD) + 1e-5f);
    __syncthreads();

    for (int c = tid; c < QSD; c += 256)
        sh[c] = (sh[c] - mean) * rstd * ln_w[c] + ln_b[c];
    __syncthreads();

    float sa2 = 0.f;
    for (int c = tid; c < NDIM; c += 256) {
        float a = 1.0f / (1.0f + expf(-sh[c]));
        sh[c] = a;
        sa2 += a * a;
    }
    red[tid] = sa2; __syncthreads();
    for (int o = 128; o > 0; o >>= 1) { if (tid < o) red[tid] += red[tid + o]; __syncthreads(); }
    const float rnorm = 1.0f / (sqrtf(red[0]) + 1e-8f);

    for (int c = tid; c < NDIM; c += 256) {
        int h = c >> 6, d = c & 63;
        float qa = sh[c] * rnorm;
        float qp = tanhf(sh[NDIM + c]) * PI_F;
        float f  = freq[h];
        float sp = shift[h];
        float Bang = CSC * f * qp;
        float Aang = Bang + CSC * sp;
        float ca, sa, cb, sb;
        sincosf(Aang, &sa, &ca);
        sincosf(Bang, &sb, &cb);
        size_t base = ((size_t)(h * LSEQ + i)) * FD;
        g_qf[base + d]      = __float2half_rn(qa * ca);
        g_qf[base + 64 + d] = __float2half_rn(qa * sa);
        g_kf[base + d]      = __float2half_rn(qa * cb);
        g_kf[base + 64 + d] = __float2half_rn(qa * sb);
        g_v[((size_t)(h * LSEQ + i)) * HDIM + d] = __float2half_rn(x[(size_t)i * NDIM + c]);
    }
}

// ---------------- tensor-core attention ----------------
#define KLD 136   // Q/K smem row stride (halves)
#define VLD 72    // V smem row stride (halves)

__global__ __launch_bounds__(128, 2)
void attn_kernel()
{
    __shared__ __align__(16) __half Ks[64 * KLD];
    __shared__ __align__(16) __half Vs[64 * VLD];

    const int h  = blockIdx.y;
    const int q0 = blockIdx.x << 6;
    const int tid  = threadIdx.x;
    const int warp = tid >> 5;
    const int lane = tid & 31;

    // ---- load Q tile into Ks, pull A-fragments into registers, then reuse buffer for K ----
    {
        const __half* qg = g_qf + ((size_t)(h * LSEQ + q0)) * FD;
        for (int idx = tid; idx < 64 * 16; idx += 128) {
            int r = idx >> 4, c = (idx & 15) << 3;
            *reinterpret_cast<uint4*>(&Ks[r * KLD + c]) =
                *reinterpret_cast<const uint4*>(&qg[(size_t)r * FD + c]);
        }
    }
    __syncthreads();

    uint32_t qf[8][4];
    {
        int row = warp * 16 + (lane & 15);
        int cof = (lane >> 4) << 3;
        #pragma unroll
        for (int ks = 0; ks < 8; ++ks)
            ldsm_x4(qf[ks], smem_u32(&Ks[row * KLD + ks * 16 + cof]));
    }

    float oacc[8][4] = {};
    float rl0 = 0.f, rl1 = 0.f;

    for (int kt = 0; kt < LSEQ / 64; ++kt) {
        const int k0 = kt << 6;
        __syncthreads();
        {
            const __half* kg = g_kf + ((size_t)(h * LSEQ + k0)) * FD;
            for (int idx = tid; idx < 64 * 16; idx += 128) {
                int r = idx >> 4, c = (idx & 15) << 3;
                *reinterpret_cast<uint4*>(&Ks[r * KLD + c]) =
                    *reinterpret_cast<const uint4*>(&kg[(size_t)r * FD + c]);
            }
            const __half* vg = g_v + ((size_t)(h * LSEQ + k0)) * HDIM;
            for (int idx = tid; idx < 64 * 8; idx += 128) {
                int r = idx >> 3, c = (idx & 7) << 3;
                *reinterpret_cast<uint4*>(&Vs[r * VLD + c]) =
                    *reinterpret_cast<const uint4*>(&vg[(size_t)r * HDIM + c]);
            }
        }
        __syncthreads();

        // ---- S = Q' K'^T ----
        float sacc[8][4] = {};
        #pragma unroll
        for (int sp = 0; sp < 4; ++sp) {
            #pragma unroll
            for (int nt = 0; nt < 8; ++nt) {
                uint32_t kf[4];
                ldsm_x4(kf, smem_u32(&Ks[(nt * 8 + (lane & 7)) * KLD
                                         + sp * 32 + ((lane >> 3) << 3)]));
                mma16816(sacc[nt], qf[2 * sp][0], qf[2 * sp][1], qf[2 * sp][2], qf[2 * sp][3],
                         kf[0], kf[1]);
                mma16816(sacc[nt], qf[2 * sp + 1][0], qf[2 * sp + 1][1],
                         qf[2 * sp + 1][2], qf[2 * sp + 1][3], kf[2], kf[3]);
            }
        }

        // ---- P = exp(S/8); rowsum; repack C-frags as fp16 A-frags ----
        uint32_t pf[8][2];
        #pragma unroll
        for (int nt = 0; nt < 8; ++nt) {
            float e0 = __expf(sacc[nt][0] * 0.125f);
            float e1 = __expf(sacc[nt][1] * 0.125f);
            float e2 = __expf(sacc[nt][2] * 0.125f);
            float e3 = __expf(sacc[nt][3] * 0.125f);
            rl0 += e0 + e1;
            rl1 += e2 + e3;
            pf[nt][0] = pack_h2(e0, e1);
            pf[nt][1] = pack_h2(e2, e3);
        }

        // ---- O += P @ V ----
        #pragma unroll
        for (int sp = 0; sp < 2; ++sp) {
            int vrow = sp * 32 + ((lane >> 3) << 3) + (lane & 7);
            #pragma unroll
            for (int nt = 0; nt < 8; ++nt) {
                uint32_t vf[4];
                ldsm_x4_t(vf, smem_u32(&Vs[vrow * VLD + nt * 8]));
                mma16816(oacc[nt], pf[4 * sp][0], pf[4 * sp][1],
                         pf[4 * sp + 1][0], pf[4 * sp + 1][1], vf[0], vf[1]);
                mma16816(oacc[nt], pf[4 * sp + 2][0], pf[4 * sp + 2][1],
                         pf[4 * sp + 3][0], pf[4 * sp + 3][1], vf[2], vf[3]);
            }
        }
    }

    // ---- reduce rowsums, normalize, store hi/lo fp16 into gathered [2048][512] layout ----
    rl0 += __shfl_xor_sync(0xffffffffu, rl0, 1);
    rl0 += __shfl_xor_sync(0xffffffffu, rl0, 2);
    rl1 += __shfl_xor_sync(0xffffffffu, rl1, 1);
    rl1 += __shfl_xor_sync(0xffffffffu, rl1, 2);
    const float inv0 = 1.0f / rl0;
    const float inv1 = 1.0f / rl1;

    const int g   = lane >> 2;
    const int tig = lane & 3;
    const int row0 = q0 + warp * 16 + g;      // sequence row
    #pragma unroll
    for (int nt = 0; nt < 8; ++nt) {
        int col = h * HDIM + nt * 8 + tig * 2;
        float o00 = oacc[nt][0] * inv0, o01 = oacc[nt][1] * inv0;
        float o10 = oacc[nt][2] * inv1, o11 = oacc[nt][3] * inv1;
        __half h00 = __float2half_rn(o00), h01 = __float2half_rn(o01);
        __half h10 = __float2half_rn(o10), h11 = __float2half_rn(o11);
        __half l00 = __float2half_rn(o00 - __half2float(h00));
        __half l01 = __float2half_rn(o01 - __half2float(h01));
        __half l10 = __float2half_rn(o10 - __half2float(h10));
        __half l11 = __float2half_rn(o11 - __half2float(h11));
        *reinterpret_cast<__half2*>(&g_aoh[(size_t)row0 * NDIM + col]) = __halves2half2(h00, h01);
        *reinterpret_cast<__half2*>(&g_aol[(size_t)row0 * NDIM + col]) = __halves2half2(l00, l01);
        *reinterpret_cast<__half2*>(&g_aoh[(size_t)(row0 + 8) * NDIM + col]) = __halves2half2(h10, h11);
        *reinterpret_cast<__half2*>(&g_aol[(size_t)(row0 + 8) * NDIM + col]) = __halves2half2(l10, l11);
    }
}

// ---------------- launch ----------------
extern "C" void kernel_launch(void* const* d_in, const int* in_sizes, int n_in,
                              void* d_out, int out_size)
{
    const float* x     = (const float*)d_in[0];
    const float* W_qs  = (const float*)d_in[1];
    const float* b_qs  = (const float*)d_in[2];
    const float* ln_w  = (const float*)d_in[3];
    const float* ln_b  = (const float*)d_in[4];
    const float* freq  = (const float*)d_in[5];
    const float* phs   = (const float*)d_in[6];
    const float* W_out = (const float*)d_in[7];
    const float* b_out = (const float*)d_in[8];
    float* out = (float*)d_out;

    void *p_qs, *p_xh, *p_xl, *p_w1h, *p_w1l, *p_woh, *p_wol, *p_aoh, *p_aol;
    cudaGetSymbolAddress(&p_qs, g_qs);
    cudaGetSymbolAddress(&p_xh, g_xh);   cudaGetSymbolAddress(&p_xl, g_xl);
    cudaGetSymbolAddress(&p_w1h, g_w1h); cudaGetSymbolAddress(&p_w1l, g_w1l);
    cudaGetSymbolAddress(&p_woh, g_woh); cudaGetSymbolAddress(&p_wol, g_wol);
    cudaGetSymbolAddress(&p_aoh, g_aoh); cudaGetSymbolAddress(&p_aol, g_aol);

    // 0) split/transpose prep
    split_kernel<<<(LSEQ * NDIM + 255) / 256, 256>>>(x, (__half*)p_xh, (__half*)p_xl,
                                                     LSEQ * NDIM);
    split_tr_kernel<<<(NDIM * QSD + 255) / 256, 256>>>(W_qs, (__half*)p_w1h, (__half*)p_w1l,
                                                       NDIM, QSD);
    split_tr_kernel<<<(NDIM * NDIM + 255) / 256, 256>>>(W_out, (__half*)p_woh, (__half*)p_wol,
                                                        NDIM, NDIM);

    // 1) qs = x @ W_qs + b_qs   [2048,1024]  (exact fp16-split HMMA)
    hmma_gemm<<<dim3(QSD / 64, LSEQ / 64), 128>>>((const __half*)p_xh, (const __half*)p_xl,
                                                  (const __half*)p_w1h, (const __half*)p_w1l,
                                                  b_qs, (float*)p_qs, QSD, NDIM);
    // 2) LN + activations + sincos features (fp16) + v scatter (fp16)
    ln_feat_kernel<<<LSEQ, 256>>>(x, ln_w, ln_b, freq, phs);
    // 3) tensor-core attention (writes split fp16 AO in gathered layout)
    attn_kernel<<<dim3(LSEQ / 64, NHEAD), 128>>>();
    // 4) out = AO @ W_out + b_out   [2048,512]  (exact fp16-split HMMA)
    hmma_gemm<<<dim3(NDIM / 64, LSEQ / 64), 128>>>((const __half*)p_aoh, (const __half*)p_aol,
                                                   (const __half*)p_woh, (const __half*)p_wol,
                                                   b_out, out, NDIM, NDIM);
}

// round 5
// speedup vs baseline: 9.9004x; 1.4037x over previous
#include <cuda_runtime.h>
#include <cuda_fp16.h>
#include <cstdint>
#include <math.h>

#define LSEQ 2048
#define NDIM 512
#define NHEAD 8
#define HDIM 64
#define QSD 1024      // 2*DIM
#define FD 128        // per-head feature dim (cos | sin)
#define PI_F 3.14159265358979323846f
#define CSC (1024.0f / 1023.0f)

// ---------------- static device scratch (no allocations) ----------------
__device__ __align__(256) float  g_qs[LSEQ * QSD];           // 8 MB
__device__ __align__(256) __half g_qf[NHEAD * LSEQ * FD];    // 4 MB
__device__ __align__(256) __half g_kf[NHEAD * LSEQ * FD];    // 4 MB
__device__ __align__(256) __half g_v [NHEAD * LSEQ * HDIM];  // 2 MB
__device__ __align__(256) __half g_xh[LSEQ * NDIM];
__device__ __align__(256) __half g_xl[LSEQ * NDIM];
__device__ __align__(256) __half g_w1h[QSD * NDIM];          // W_qs^T [N][K]
__device__ __align__(256) __half g_w1l[QSD * NDIM];
__device__ __align__(256) __half g_woh[NDIM * NDIM];         // W_out^T [N][K]
__device__ __align__(256) __half g_wol[NDIM * NDIM];
__device__ __align__(256) __half g_aoh[LSEQ * NDIM];
__device__ __align__(256) __half g_aol[LSEQ * NDIM];

// ---------------- asm helpers ----------------
__device__ __forceinline__ uint32_t smem_u32(const void* p) {
    return (uint32_t)__cvta_generic_to_shared(p);
}
__device__ __forceinline__ void ldsm_x4(uint32_t r[4], uint32_t addr) {
    asm volatile("ldmatrix.sync.aligned.m8n8.x4.shared.b16 {%0,%1,%2,%3}, [%4];"
        : "=r"(r[0]), "=r"(r[1]), "=r"(r[2]), "=r"(r[3]) : "r"(addr));
}
__device__ __forceinline__ void ldsm_x4_t(uint32_t r[4], uint32_t addr) {
    asm volatile("ldmatrix.sync.aligned.m8n8.x4.trans.shared.b16 {%0,%1,%2,%3}, [%4];"
        : "=r"(r[0]), "=r"(r[1]), "=r"(r[2]), "=r"(r[3]) : "r"(addr));
}
__device__ __forceinline__ void mma16816(float c[4], const uint32_t a0, const uint32_t a1,
                                         const uint32_t a2, const uint32_t a3,
                                         const uint32_t b0, const uint32_t b1) {
    asm volatile("mma.sync.aligned.m16n8k16.row.col.f32.f16.f16.f32 "
        "{%0,%1,%2,%3}, {%4,%5,%6,%7}, {%8,%9}, {%0,%1,%2,%3};"
        : "+f"(c[0]), "+f"(c[1]), "+f"(c[2]), "+f"(c[3])
        : "r"(a0), "r"(a1), "r"(a2), "r"(a3), "r"(b0), "r"(b1));
}
__device__ __forceinline__ uint32_t pack_h2(float x, float y) {
    __half2 h = __floats2half2_rn(x, y);
    return *reinterpret_cast<uint32_t*>(&h);
}
__device__ __forceinline__ void cp16(uint32_t dst, const void* src) {
    asm volatile("cp.async.cg.shared.global [%0], [%1], 16;" :: "r"(dst), "l"(src));
}
__device__ __forceinline__ void cp_commit() {
    asm volatile("cp.async.commit_group;");
}
__device__ __forceinline__ void cp_wait1() {
    asm volatile("cp.async.wait_group 1;");
}
__device__ __forceinline__ void cp_wait0() {
    asm volatile("cp.async.wait_group 0;");
}

// ---------------- split helpers ----------------
__global__ __launch_bounds__(256)
void split_kernel(const float* __restrict__ src, __half* __restrict__ hi,
                  __half* __restrict__ lo, int n)
{
    int i = blockIdx.x * 256 + threadIdx.x;
    if (i < n) {
        float v = src[i];
        __half h = __float2half_rn(v);
        hi[i] = h;
        lo[i] = __float2half_rn(v - __half2float(h));
    }
}

__global__ __launch_bounds__(256)
void split_tr_kernel(const float* __restrict__ src, __half* __restrict__ hi,
                     __half* __restrict__ lo, int R, int C)
{
    int i = blockIdx.x * 256 + threadIdx.x;
    if (i < R * C) {
        int c = i / R, r = i - c * R;
        float v = src[(size_t)r * C + c];
        __half h = __float2half_rn(v);
        hi[i] = h;
        lo[i] = __float2half_rn(v - __half2float(h));
    }
}

// ---------------- HMMA GEMM v2: m32-warps + 2-stage cp.async pipeline ----------------
// C[M,N] = A@B + bias. A = (Ah+Al) row-major [M][K]; B = (Bh+Bl) transposed [N][K].
// CTA tile 128x64, 4 warps (each m32 x n64). K-tile 64, double buffered.
#define GLD 72
#define G_AH 0
#define G_AL (128 * GLD)
#define G_BH (256 * GLD)
#define G_BL (320 * GLD)
#define G_STAGE_B (384 * GLD * 2)      // 55296 bytes per stage

__global__ __launch_bounds__(128)
void hmma_gemm(const __half* __restrict__ Ah, const __half* __restrict__ Al,
               const __half* __restrict__ Bh, const __half* __restrict__ Bl,
               const float* __restrict__ bias, float* __restrict__ C,
               int N, int K)
{
    extern __shared__ __half gsm[];
    const uint32_t sbase = smem_u32(gsm);

    const int tid  = threadIdx.x;
    const int warp = tid >> 5;
    const int lane = tid & 31;
    const int m0 = blockIdx.y << 7, n0 = blockIdx.x << 6;
    const int KT = K >> 6;

    float acc[2][8][4] = {};

    // stage loader: 384 logical rows x 8 16B-chunks
    auto load_stage = [&](int st, int k0) {
        uint32_t sb = sbase + st * G_STAGE_B;
        #pragma unroll 4
        for (int i = tid; i < 384 * 8; i += 128) {
            int r = i >> 3;
            int c = (i & 7) << 3;   // halves
            if (r < 128)
                cp16(sb + (G_AH + r * GLD + c) * 2,
                     Ah + (size_t)(m0 + r) * K + k0 + c);
            else if (r < 256)
                cp16(sb + (G_AL + (r - 128) * GLD + c) * 2,
                     Al + (size_t)(m0 + r - 128) * K + k0 + c);
            else if (r < 320)
                cp16(sb + (G_BH + (r - 256) * GLD + c) * 2,
                     Bh + (size_t)(n0 + r - 256) * K + k0 + c);
            else
                cp16(sb + (G_BL + (r - 320) * GLD + c) * 2,
                     Bl + (size_t)(n0 + r - 320) * K + k0 + c);
        }
    };

    load_stage(0, 0);
    cp_commit();

    for (int t = 0; t < KT; ++t) {
        if (t + 1 < KT) {
            load_stage((t + 1) & 1, (t + 1) << 6);
            cp_commit();
            cp_wait1();
        } else {
            cp_wait0();
        }
        __syncthreads();

        const uint32_t sb = sbase + (t & 1) * G_STAGE_B;

        #pragma unroll
        for (int sp2 = 0; sp2 < 2; ++sp2) {
            uint32_t fh[2][2][4], fl[2][2][4];
            #pragma unroll
            for (int rb = 0; rb < 2; ++rb) {
                int abase = (warp * 32 + rb * 16 + (lane & 15)) * GLD
                            + sp2 * 32 + ((lane >> 4) << 3);
                ldsm_x4(fh[rb][0], sb + (G_AH + abase) * 2);
                ldsm_x4(fh[rb][1], sb + (G_AH + abase + 16) * 2);
                ldsm_x4(fl[rb][0], sb + (G_AL + abase) * 2);
                ldsm_x4(fl[rb][1], sb + (G_AL + abase + 16) * 2);
            }
            #pragma unroll
            for (int nt = 0; nt < 8; ++nt) {
                int bbase = (nt * 8 + (lane & 7)) * GLD
                            + sp2 * 32 + ((lane >> 3) << 3);
                uint32_t bh[4], bl[4];
                ldsm_x4(bh, sb + (G_BH + bbase) * 2);
                ldsm_x4(bl, sb + (G_BL + bbase) * 2);
                #pragma unroll
                for (int rb = 0; rb < 2; ++rb) {
                    mma16816(acc[rb][nt], fh[rb][0][0], fh[rb][0][1], fh[rb][0][2], fh[rb][0][3], bh[0], bh[1]);
                    mma16816(acc[rb][nt], fh[rb][1][0], fh[rb][1][1], fh[rb][1][2], fh[rb][1][3], bh[2], bh[3]);
                    mma16816(acc[rb][nt], fh[rb][0][0], fh[rb][0][1], fh[rb][0][2], fh[rb][0][3], bl[0], bl[1]);
                    mma16816(acc[rb][nt], fh[rb][1][0], fh[rb][1][1], fh[rb][1][2], fh[rb][1][3], bl[2], bl[3]);
                    mma16816(acc[rb][nt], fl[rb][0][0], fl[rb][0][1], fl[rb][0][2], fl[rb][0][3], bh[0], bh[1]);
                    mma16816(acc[rb][nt], fl[rb][1][0], fl[rb][1][1], fl[rb][1][2], fl[rb][1][3], bh[2], bh[3]);
                }
            }
        }
        __syncthreads();
    }

    const int g   = lane >> 2;
    const int tig = lane & 3;
    #pragma unroll
    for (int rb = 0; rb < 2; ++rb) {
        int row0 = m0 + warp * 32 + rb * 16 + g;
        #pragma unroll
        for (int nt = 0; nt < 8; ++nt) {
            int col = n0 + nt * 8 + tig * 2;
            C[(size_t)row0 * N + col]           = acc[rb][nt][0] + bias[col];
            C[(size_t)row0 * N + col + 1]       = acc[rb][nt][1] + bias[col + 1];
            C[(size_t)(row0 + 8) * N + col]     = acc[rb][nt][2] + bias[col];
            C[(size_t)(row0 + 8) * N + col + 1] = acc[rb][nt][3] + bias[col + 1];
        }
    }
}

// ---------------- LN + activations + features (warp-shuffle reductions) ----------------
__global__ __launch_bounds__(256)
void ln_feat_kernel(const float* __restrict__ x,
                    const float* __restrict__ ln_w, const float* __restrict__ ln_b,
                    const float* __restrict__ freq, const float* __restrict__ shift)
{
    const int i = blockIdx.x;
    const int tid = threadIdx.x;
    const int lane = tid & 31, warp = tid >> 5;
    __shared__ float sh[QSD];
    __shared__ float redA[8], redB[8];
    __shared__ float bcast[2];

    float4 v = reinterpret_cast<const float4*>(g_qs + (size_t)i * QSD)[tid];
    reinterpret_cast<float4*>(sh)[tid] = v;
    float s  = v.x + v.y + v.z + v.w;
    float s2 = v.x * v.x + v.y * v.y + v.z * v.z + v.w * v.w;
    #pragma unroll
    for (int o = 16; o; o >>= 1) {
        s  += __shfl_xor_sync(0xffffffffu, s, o);
        s2 += __shfl_xor_sync(0xffffffffu, s2, o);
    }
    if (!lane) { redA[warp] = s; redB[warp] = s2; }
    __syncthreads();
    if (tid == 0) {
        float a = 0.f, b = 0.f;
        #pragma unroll
        for (int w = 0; w < 8; ++w) { a += redA[w]; b += redB[w]; }
        float mean = a * (1.0f / QSD);
        float var  = b * (1.0f / QSD) - mean * mean;
        bcast[0] = mean;
        bcast[1] = rsqrtf(var + 1e-5f);
    }
    __syncthreads();
    const float mean = bcast[0], rstd = bcast[1];

    // amp channels c0 = 2*tid, 2*tid+1 (first 512)
    float a0, a1;
    {
        float2 ap = reinterpret_cast<const float2*>(sh)[tid];
        float2 w  = reinterpret_cast<const float2*>(ln_w)[tid];
        float2 b  = reinterpret_cast<const float2*>(ln_b)[tid];
        float n0 = (ap.x - mean) * rstd * w.x + b.x;
        float n1 = (ap.y - mean) * rstd * w.y + b.y;
        a0 = 1.0f / (1.0f + expf(-n0));
        a1 = 1.0f / (1.0f + expf(-n1));
    }
    float sa2 = a0 * a0 + a1 * a1;
    #pragma unroll
    for (int o = 16; o; o >>= 1) sa2 += __shfl_xor_sync(0xffffffffu, sa2, o);
    if (!lane) redA[warp] = sa2;
    __syncthreads();
    if (tid == 0) {
        float t = 0.f;
        #pragma unroll
        for (int w = 0; w < 8; ++w) t += redA[w];
        bcast[0] = 1.0f / (sqrtf(t) + 1e-8f);
    }
    __syncthreads();
    const float rnorm = bcast[0];

    // phase channels
    float2 pp = reinterpret_cast<const float2*>(sh + NDIM)[tid];
    float2 pw = reinterpret_cast<const float2*>(ln_w + NDIM)[tid];
    float2 pb = reinterpret_cast<const float2*>(ln_b + NDIM)[tid];
    float qp0 = tanhf((pp.x - mean) * rstd * pw.x + pb.x) * PI_F;
    float qp1 = tanhf((pp.y - mean) * rstd * pw.y + pb.y) * PI_F;

    const int c0 = tid * 2;
    const int h = c0 >> 6, d = c0 & 63;
    const float f  = freq[h];
    const float sp = shift[h];
    const float qa0 = a0 * rnorm, qa1 = a1 * rnorm;

    float B0 = CSC * f * qp0, B1 = CSC * f * qp1;
    float A0 = B0 + CSC * sp, A1 = B1 + CSC * sp;
    float ca0, sa0, cb0, sb0, ca1, sa1, cb1, sb1;
    sincosf(A0, &sa0, &ca0); sincosf(B0, &sb0, &cb0);
    sincosf(A1, &sa1, &ca1); sincosf(B1, &sb1, &cb1);

    size_t base = ((size_t)(h * LSEQ + i)) * FD;
    *reinterpret_cast<__half2*>(&g_qf[base + d])      = __floats2half2_rn(qa0 * ca0, qa1 * ca1);
    *reinterpret_cast<__half2*>(&g_qf[base + 64 + d]) = __floats2half2_rn(qa0 * sa0, qa1 * sa1);
    *reinterpret_cast<__half2*>(&g_kf[base + d])      = __floats2half2_rn(qa0 * cb0, qa1 * cb1);
    *reinterpret_cast<__half2*>(&g_kf[base + 64 + d]) = __floats2half2_rn(qa0 * sb0, qa1 * sb1);

    float2 xv = reinterpret_cast<const float2*>(x + (size_t)i * NDIM)[tid];
    *reinterpret_cast<__half2*>(&g_v[((size_t)(h * LSEQ + i)) * HDIM + d]) =
        __floats2half2_rn(xv.x, xv.y);
}

// ---------------- tensor-core attention with 2-stage cp.async pipeline ----------------
#define KLD 136
#define VLD 72
#define A_VOFF (64 * KLD)                 // halves
#define A_STAGE_B ((64 * KLD + 64 * VLD) * 2)   // 26624 bytes

__global__ __launch_bounds__(128, 2)
void attn_kernel()
{
    extern __shared__ __half asm_smem[];
    const uint32_t sbase = smem_u32(asm_smem);

    const int h  = blockIdx.y;
    const int q0 = blockIdx.x << 6;
    const int tid  = threadIdx.x;
    const int warp = tid >> 5;
    const int lane = tid & 31;

    // ---- stage Q into stage0 K region, pull frags ----
    {
        const __half* qg = g_qf + ((size_t)(h * LSEQ + q0)) * FD;
        for (int idx = tid; idx < 64 * 16; idx += 128) {
            int r = idx >> 4, c = (idx & 15) << 3;
            *reinterpret_cast<uint4*>(&asm_smem[r * KLD + c]) =
                *reinterpret_cast<const uint4*>(&qg[(size_t)r * FD + c]);
        }
    }
    __syncthreads();

    uint32_t qf[8][4];
    {
        int row = warp * 16 + (lane & 15);
        int cof = (lane >> 4) << 3;
        #pragma unroll
        for (int ks = 0; ks < 8; ++ks)
            ldsm_x4(qf[ks], sbase + (row * KLD + ks * 16 + cof) * 2);
    }
    __syncthreads();   // frags pulled before stage0 is overwritten

    auto load_tile = [&](int st, int k0) {
        uint32_t sb = sbase + st * A_STAGE_B;
        const __half* kg = g_kf + ((size_t)(h * LSEQ + k0)) * FD;
        const __half* vg = g_v  + ((size_t)(h * LSEQ + k0)) * HDIM;
        #pragma unroll 4
        for (int i = tid; i < 64 * 16; i += 128) {
            int r = i >> 4, c = (i & 15) << 3;
            cp16(sb + (r * KLD + c) * 2, kg + (size_t)r * FD + c);
        }
        #pragma unroll 2
        for (int i = tid; i < 64 * 8; i += 128) {
            int r = i >> 3, c = (i & 7) << 3;
            cp16(sb + (A_VOFF + r * VLD + c) * 2, vg + (size_t)r * HDIM + c);
        }
    };

    float oacc[8][4] = {};
    float rl0 = 0.f, rl1 = 0.f;

    load_tile(0, 0);
    cp_commit();

    const int NT = LSEQ / 64;
    for (int kt = 0; kt < NT; ++kt) {
        if (kt + 1 < NT) {
            load_tile((kt + 1) & 1, (kt + 1) << 6);
            cp_commit();
            cp_wait1();
        } else {
            cp_wait0();
        }
        __syncthreads();

        const uint32_t sb = sbase + (kt & 1) * A_STAGE_B;

        // ---- S = Q' K'^T ----
        float sacc[8][4] = {};
        #pragma unroll
        for (int sp = 0; sp < 4; ++sp) {
            #pragma unroll
            for (int nt = 0; nt < 8; ++nt) {
                uint32_t kf[4];
                ldsm_x4(kf, sb + ((nt * 8 + (lane & 7)) * KLD
                                  + sp * 32 + ((lane >> 3) << 3)) * 2);
                mma16816(sacc[nt], qf[2 * sp][0], qf[2 * sp][1], qf[2 * sp][2], qf[2 * sp][3],
                         kf[0], kf[1]);
                mma16816(sacc[nt], qf[2 * sp + 1][0], qf[2 * sp + 1][1],
                         qf[2 * sp + 1][2], qf[2 * sp + 1][3], kf[2], kf[3]);
            }
        }

        // ---- P = exp(S/8); rowsum; repack as A-frags ----
        uint32_t pf[8][2];
        #pragma unroll
        for (int nt = 0; nt < 8; ++nt) {
            float e0 = __expf(sacc[nt][0] * 0.125f);
            float e1 = __expf(sacc[nt][1] * 0.125f);
            float e2 = __expf(sacc[nt][2] * 0.125f);
            float e3 = __expf(sacc[nt][3] * 0.125f);
            rl0 += e0 + e1;
            rl1 += e2 + e3;
            pf[nt][0] = pack_h2(e0, e1);
            pf[nt][1] = pack_h2(e2, e3);
        }

        // ---- O += P @ V ----
        #pragma unroll
        for (int sp = 0; sp < 2; ++sp) {
            int vrow = sp * 32 + ((lane >> 3) << 3) + (lane & 7);
            #pragma unroll
            for (int nt = 0; nt < 8; ++nt) {
                uint32_t vf[4];
                ldsm_x4_t(vf, sb + (A_VOFF + vrow * VLD + nt * 8) * 2);
                mma16816(oacc[nt], pf[4 * sp][0], pf[4 * sp][1],
                         pf[4 * sp + 1][0], pf[4 * sp + 1][1], vf[0], vf[1]);
                mma16816(oacc[nt], pf[4 * sp + 2][0], pf[4 * sp + 2][1],
                         pf[4 * sp + 3][0], pf[4 * sp + 3][1], vf[2], vf[3]);
            }
        }
        __syncthreads();
    }

    // ---- reduce rowsums, normalize, store split fp16 gathered [2048][512] ----
    rl0 += __shfl_xor_sync(0xffffffffu, rl0, 1);
    rl0 += __shfl_xor_sync(0xffffffffu, rl0, 2);
    rl1 += __shfl_xor_sync(0xffffffffu, rl1, 1);
    rl1 += __shfl_xor_sync(0xffffffffu, rl1, 2);
    const float inv0 = 1.0f / rl0;
    const float inv1 = 1.0f / rl1;

    const int g   = lane >> 2;
    const int tig = lane & 3;
    const int row0 = q0 + warp * 16 + g;
    #pragma unroll
    for (int nt = 0; nt < 8; ++nt) {
        int col = h * HDIM + nt * 8 + tig * 2;
        float o00 = oacc[nt][0] * inv0, o01 = oacc[nt][1] * inv0;
        float o10 = oacc[nt][2] * inv1, o11 = oacc[nt][3] * inv1;
        __half h00 = __float2half_rn(o00), h01 = __float2half_rn(o01);
        __half h10 = __float2half_rn(o10), h11 = __float2half_rn(o11);
        __half l00 = __float2half_rn(o00 - __half2float(h00));
        __half l01 = __float2half_rn(o01 - __half2float(h01));
        __half l10 = __float2half_rn(o10 - __half2float(h10));
        __half l11 = __float2half_rn(o11 - __half2float(h11));
        *reinterpret_cast<__half2*>(&g_aoh[(size_t)row0 * NDIM + col]) = __halves2half2(h00, h01);
        *reinterpret_cast<__half2*>(&g_aol[(size_t)row0 * NDIM + col]) = __halves2half2(l00, l01);
        *reinterpret_cast<__half2*>(&g_aoh[(size_t)(row0 + 8) * NDIM + col]) = __halves2half2(h10, h11);
        *reinterpret_cast<__half2*>(&g_aol[(size_t)(row0 + 8) * NDIM + col]) = __halves2half2(l10, l11);
    }
}

// ---------------- launch ----------------
extern "C" void kernel_launch(void* const* d_in, const int* in_sizes, int n_in,
                              void* d_out, int out_size)
{
    const float* x     = (const float*)d_in[0];
    const float* W_qs  = (const float*)d_in[1];
    const float* b_qs  = (const float*)d_in[2];
    const float* ln_w  = (const float*)d_in[3];
    const float* ln_b  = (const float*)d_in[4];
    const float* freq  = (const float*)d_in[5];
    const float* phs   = (const float*)d_in[6];
    const float* W_out = (const float*)d_in[7];
    const float* b_out = (const float*)d_in[8];
    float* out = (float*)d_out;

    void *p_qs, *p_xh, *p_xl, *p_w1h, *p_w1l, *p_woh, *p_wol, *p_aoh, *p_aol;
    cudaGetSymbolAddress(&p_qs, g_qs);
    cudaGetSymbolAddress(&p_xh, g_xh);   cudaGetSymbolAddress(&p_xl, g_xl);
    cudaGetSymbolAddress(&p_w1h, g_w1h); cudaGetSymbolAddress(&p_w1l, g_w1l);
    cudaGetSymbolAddress(&p_woh, g_woh); cudaGetSymbolAddress(&p_wol, g_wol);
    cudaGetSymbolAddress(&p_aoh, g_aoh); cudaGetSymbolAddress(&p_aol, g_aol);

    const int gemm_smem = 2 * G_STAGE_B;             // 110592 B
    const int attn_smem = 2 * A_STAGE_B;             // 53248 B
    cudaFuncSetAttribute(hmma_gemm, cudaFuncAttributeMaxDynamicSharedMemorySize, gemm_smem);
    cudaFuncSetAttribute(attn_kernel, cudaFuncAttributeMaxDynamicSharedMemorySize, attn_smem);

    // 0) split/transpose prep
    split_kernel<<<(LSEQ * NDIM + 255) / 256, 256>>>(x, (__half*)p_xh, (__half*)p_xl,
                                                     LSEQ * NDIM);
    split_tr_kernel<<<(NDIM * QSD + 255) / 256, 256>>>(W_qs, (__half*)p_w1h, (__half*)p_w1l,
                                                       NDIM, QSD);
    split_tr_kernel<<<(NDIM * NDIM + 255) / 256, 256>>>(W_out, (__half*)p_woh, (__half*)p_wol,
                                                        NDIM, NDIM);

    // 1) qs = x @ W_qs + b_qs   [2048,1024]
    hmma_gemm<<<dim3(QSD / 64, LSEQ / 128), 128, gemm_smem>>>(
        (const __half*)p_xh, (const __half*)p_xl,
        (const __half*)p_w1h, (const __half*)p_w1l,
        b_qs, (float*)p_qs, QSD, NDIM);
    // 2) LN + activations + features
    ln_feat_kernel<<<LSEQ, 256>>>(x, ln_w, ln_b, freq, phs);
    // 3) attention
    attn_kernel<<<dim3(LSEQ / 64, NHEAD), 128, attn_smem>>>();
    // 4) out = AO @ W_out + b_out   [2048,512]
    hmma_gemm<<<dim3(NDIM / 64, LSEQ / 128), 128, gemm_smem>>>(
        (const __half*)p_aoh, (const __half*)p_aol,
        (const __half*)p_woh, (const __half*)p_wol,
        b_out, out, NDIM, NDIM);
}